// round 5
// baseline (speedup 1.0000x reference)
#include <cuda_runtime.h>

#define N_FULL   50000
#define NLAT     10
#define MU       32
#define BATCH    8
#define NODES    16        // nodes per block (grid = 3125 exactly covers 50000)
#define MSTR     17        // m-stride in G/W2
#define ISTR     545       // i-stride (545 mod 32 = 17 -> bank gets 17i term)
#define GSZ      (NLAT * ISTR)   // 5450 floats

// Scratch (static __device__ arrays: no dynamic allocation allowed)
__device__ float g_encoded[BATCH * NLAT];
__device__ __align__(128) float g_dec4[N_FULL * 16];   // 64B rows [v0..v9,pad6]

// ---------------------------------------------------------------------------
// Kernel 1 (fused): blocks 0..79 compute encoded[b,i] directly (no atomics,
// no zero-init). Blocks 80..275 transpose decoder [n,N] -> [N,16] 64B rows.
// ---------------------------------------------------------------------------
__global__ void __launch_bounds__(256)
prep_encode_kernel(const float* __restrict__ x,
                   const float* __restrict__ ew,
                   const float* __restrict__ decoder) {
    if (blockIdx.x < BATCH * NLAT) {
        const int b = blockIdx.x / NLAT;
        const int i = blockIdx.x % NLAT;
        const float4* xr = (const float4*)(x  + (size_t)b * N_FULL);
        const float4* wr = (const float4*)(ew + (size_t)i * N_FULL);
        float acc = 0.0f;
        for (int t = threadIdx.x; t < N_FULL / 4; t += 256) {
            float4 a = __ldg(xr + t);
            float4 c = __ldg(wr + t);
            acc = fmaf(a.x, c.x, acc);
            acc = fmaf(a.y, c.y, acc);
            acc = fmaf(a.z, c.z, acc);
            acc = fmaf(a.w, c.w, acc);
        }
#pragma unroll
        for (int d = 16; d > 0; d >>= 1)
            acc += __shfl_xor_sync(0xffffffffu, acc, d);
        __shared__ float red[8];
        int lane = threadIdx.x & 31, warp = threadIdx.x >> 5;
        if (lane == 0) red[warp] = acc;
        __syncthreads();
        if (threadIdx.x == 0) {
            float s = 0.0f;
#pragma unroll
            for (int w = 0; w < 8; w++) s += red[w];
            g_encoded[blockIdx.x] = s;
        }
    } else {
        int p = (blockIdx.x - BATCH * NLAT) * 256 + threadIdx.x;
        if (p < N_FULL) {
            float v[NLAT];
#pragma unroll
            for (int i = 0; i < NLAT; i++)
                v[i] = __ldg(decoder + (size_t)i * N_FULL + p);
            float4* dst = (float4*)(g_dec4 + (size_t)p * 16);
            dst[0] = make_float4(v[0], v[1], v[2], v[3]);
            dst[1] = make_float4(v[4], v[5], v[6], v[7]);
            dst[2] = make_float4(v[8], v[9], 0.0f, 0.0f);
            dst[3] = make_float4(0.0f, 0.0f, 0.0f, 0.0f);
        }
    }
}

// ---------------------------------------------------------------------------
// Kernel 2: main. Block = 256 threads, 16 nodes, SINGLE i-pass (all 10).
//
//  Phase A (gather): 4 lanes/row on 64B decoder rows (q=0,1,2 carry data);
//    one warp LDG.128 covers 8 random rows = 8 line-touches: the floor of
//    1 L1 wavefront per neighbour row, once (vs twice in R4).
//  Phase B (scan): 160 tasks (i,j), one round: G <- prefix(g),
//    W2 <- prefix(m^2 g). Banks (17i+17m+j)%32 conflict-free.
//  Phase C: warp = batch b, lane = ihalf*16+j; each thread does 5 latent
//    dims with the closed-form bubble window
//      smoothed = (Pg[cnt-1] - inv2*Pm2[cnt-1]) / (cnt - inv2*S2(cnt));
//    halves combined by one shfl_down(16). No trailing barrier.
//  PDL: neighbour tile loads precede cudaGridDependencySynchronize().
// ---------------------------------------------------------------------------
__global__ void __launch_bounds__(256, 4)
main_kernel(const float* __restrict__ enc_b,
            const float* __restrict__ bw,
            const int*   __restrict__ neigh,
            float*       __restrict__ out) {
    __shared__ float G[GSZ];
    __shared__ float W2[GSZ];
    __shared__ unsigned short NB[NODES * MU];   // neighbour idx < 50000 < 2^16

    const int tid    = threadIdx.x;
    const int lane   = tid & 31;
    const int warp   = tid >> 5;
    const int p_base = blockIdx.x * NODES;

    // ---- neighbour tile (independent of prep kernel: load before PDL sync)
    {
        int2 v = *(const int2*)(neigh + p_base * MU + tid * 2);
        NB[tid * 2 + 0] = (unsigned short)v.x;
        NB[tid * 2 + 1] = (unsigned short)v.y;
    }
#if defined(__CUDA_ARCH__) && (__CUDA_ARCH__ >= 900)
    cudaGridDependencySynchronize();   // wait for prep_encode results
#endif
    __syncthreads();

    // ---- Phase A: cooperative gather (64 rows/warp, 8 rows per LDG) ----
    {
        const int q  = lane & 3;       // 16B quarter of the 64B row
        const int rl = lane >> 2;      // row-in-instruction 0..7
#pragma unroll
        for (int t = 0; t < 8; t++) {
            const int r = warp * 64 + t * 8 + rl;  // flat row: j = r>>5, m = r&31
            const int m = r & 31;
            const int j = r >> 5;
            const int nb = NB[r];
            if (q < 3) {
                float4 v = __ldg((const float4*)g_dec4 + nb * 4 + q);
                const int a0 = (4 * q) * ISTR + m * MSTR + j;
                G[a0] = v.x;
                G[a0 + ISTR] = v.y;
                if (q < 2) {
                    G[a0 + 2 * ISTR] = v.z;
                    G[a0 + 3 * ISTR] = v.w;
                }
            }
        }
    }
    __syncthreads();

    // ---- Phase B: inclusive prefix over m (160 tasks, one round) ----
    if (tid < NLAT * NODES) {
        const int i = tid >> 4;
        const int j = tid & 15;
        const int base = i * ISTR + j;
        float pg = 0.0f, pm = 0.0f;
#pragma unroll
        for (int m = 0; m < MU; m++) {
            float v = G[base + m * MSTR];
            pg += v;
            pm = fmaf((float)(m * m), v, pm);
            G [base + m * MSTR] = pg;
            W2[base + m * MSTR] = pm;
        }
    }
    __syncthreads();

    // ---- Phase C: warp = batch b; lane = ihalf*16 + j ----
    const int b     = warp;
    const int ihalf = lane >> 4;
    const int j     = lane & 15;
    const int p     = p_base + j;

    float encb[NLAT];
#pragma unroll
    for (int k = 0; k < NLAT; k++)
        encb[k] = g_encoded[b * NLAT + k] + __ldg(enc_b + k);

    const float* bwp = bw + p;
    float acc = 0.0f;
#pragma unroll
    for (int ii = 0; ii < 5; ii++) {
        const int i = ihalf * 5 + ii;
        float z = 0.0f;
#pragma unroll
        for (int k = 0; k < NLAT; k++)
            z = fmaf(encb[k], __ldg(bwp + (size_t)(i * NLAT + k) * N_FULL), z);

        float e    = __expf(-z);
        float tt   = 1.0f + e;                              // = 1/w
        float u    = __fdividef((float)MU, tt);             // = MU*w
        int   cnt  = min(MU, (int)u + 1);                   // #active m
        float inv2 = tt * tt * (1.0f / (float)(MU * MU));   // 1/(MU*w)^2

        const int base = i * ISTR + (cnt - 1) * MSTR + j;
        float Pg = G[base];
        float Pm = W2[base];
        int   c1 = cnt - 1;
        float S2 = (float)(c1 * cnt * (2 * cnt - 1)) * (1.0f / 6.0f);
        float s  = (float)cnt - inv2 * S2;
        float smv = __fdividef(fmaf(-inv2, Pm, Pg), s);
        acc = fmaf(encb[i], smv, acc);
    }

    // combine the two 5-dim halves within the warp
    acc += __shfl_down_sync(0xffffffffu, acc, 16);
    if (ihalf == 0)
        out[(size_t)b * N_FULL + p] = acc;
}

// ---------------------------------------------------------------------------
extern "C" void kernel_launch(void* const* d_in, const int* in_sizes, int n_in,
                              void* d_out, int out_size) {
    const float* x       = (const float*)d_in[0];
    const float* enc_w   = (const float*)d_in[1];
    const float* enc_b   = (const float*)d_in[2];
    const float* decoder = (const float*)d_in[3];
    const float* bw      = (const float*)d_in[4];
    const int*   neigh   = (const int*)  d_in[5];
    float*       out     = (float*)d_out;
    (void)in_sizes; (void)n_in; (void)out_size;

    const int tp_blocks = (N_FULL + 255) / 256;                 // 196
    prep_encode_kernel<<<BATCH * NLAT + tp_blocks, 256>>>(x, enc_w, decoder);

    // main with PDL: overlap its launch/prologue with prep_encode execution
    cudaLaunchConfig_t cfg = {};
    cfg.gridDim  = dim3(N_FULL / NODES);   // 3125, exact
    cfg.blockDim = dim3(256);
    cfg.dynamicSmemBytes = 0;
    cfg.stream = 0;
    cudaLaunchAttribute attr[1];
    attr[0].id = cudaLaunchAttributeProgrammaticStreamSerialization;
    attr[0].val.programmaticStreamSerializationAllowed = 1;
    cfg.attrs = attr;
    cfg.numAttrs = 1;
    if (cudaLaunchKernelEx(&cfg, main_kernel, enc_b, bw, neigh, out)
        != cudaSuccess) {
        main_kernel<<<N_FULL / NODES, 256>>>(enc_b, bw, neigh, out);
    }
}

// round 6
// speedup vs baseline: 1.7814x; 1.7814x over previous
#include <cuda_runtime.h>

#define N_FULL   50000
#define NLAT     10
#define MU       32
#define BATCH    8
#define NODES    32
#define MSTR     33               // m-stride in G/W2
#define ISTR     1058             // i-stride = 32*33+2 (mod 32 == 2)
#define GSZ      (NLAT * ISTR)    // 10580 floats per array

// Scratch (static __device__ arrays: no dynamic allocation allowed)
__device__ float g_encoded[BATCH * NLAT];                 // bias pre-added
__device__ __align__(128) float g_dec4[N_FULL * 16];      // 64B rows [v0..v9,pad6]

// ---------------------------------------------------------------------------
// Kernel 1 (fused): blocks 0..79 compute encoded[b,i] + enc_b[i] directly.
// Blocks 80..275 transpose decoder [n,N] -> [N,16] (64B-aligned rows).
// ---------------------------------------------------------------------------
__global__ void __launch_bounds__(256)
prep_encode_kernel(const float* __restrict__ x,
                   const float* __restrict__ ew,
                   const float* __restrict__ enc_b,
                   const float* __restrict__ decoder) {
    if (blockIdx.x < BATCH * NLAT) {
        const int b = blockIdx.x / NLAT;
        const int i = blockIdx.x % NLAT;
        const float4* xr = (const float4*)(x  + (size_t)b * N_FULL);
        const float4* wr = (const float4*)(ew + (size_t)i * N_FULL);
        float acc = 0.0f;
        for (int t = threadIdx.x; t < N_FULL / 4; t += 256) {
            float4 a = __ldg(xr + t);
            float4 c = __ldg(wr + t);
            acc = fmaf(a.x, c.x, acc);
            acc = fmaf(a.y, c.y, acc);
            acc = fmaf(a.z, c.z, acc);
            acc = fmaf(a.w, c.w, acc);
        }
#pragma unroll
        for (int d = 16; d > 0; d >>= 1)
            acc += __shfl_xor_sync(0xffffffffu, acc, d);
        __shared__ float red[8];
        int lane = threadIdx.x & 31, warp = threadIdx.x >> 5;
        if (lane == 0) red[warp] = acc;
        __syncthreads();
        if (threadIdx.x == 0) {
            float s = 0.0f;
#pragma unroll
            for (int w = 0; w < 8; w++) s += red[w];
            g_encoded[blockIdx.x] = s + __ldg(enc_b + i);   // bias folded in
        }
    } else {
        int p = (blockIdx.x - BATCH * NLAT) * 256 + threadIdx.x;
        if (p < N_FULL) {
            float v[NLAT];
#pragma unroll
            for (int i = 0; i < NLAT; i++)
                v[i] = __ldg(decoder + (size_t)i * N_FULL + p);
            float4* dst = (float4*)(g_dec4 + (size_t)p * 16);
            dst[0] = make_float4(v[0], v[1], v[2], v[3]);
            dst[1] = make_float4(v[4], v[5], v[6], v[7]);
            dst[2] = make_float4(v[8], v[9], 0.0f, 0.0f);
            dst[3] = make_float4(0.0f, 0.0f, 0.0f, 0.0f);
        }
    }
}

// ---------------------------------------------------------------------------
// Kernel 2: main. 512 threads (16 warps), 32 nodes/block, single i-pass.
// 87.7KB dynamic smem -> 2 CTAs/SM x 16 warps = 32 warps/SM.
//
//  Phase A (gather): 1024 rows/block, 4 lanes per 64B decoder row (q=0..2
//    carry the 10 values): one warp-LDG touches 8 random rows = 8 lines =
//    8 wavefronts -> the floor of 1 wavefront per neighbour row, ONCE.
//    Scatter banks (8q+2u+m+j)%32: conflict-free.
//  Phase B (scan): 320 tasks (i = warp, j = lane): G <- prefix(g),
//    W2 <- prefix(m^2 g) over m. Banks (2i+m+j)%32: conflict-free.
//  Phase C: warp = (b, ihalf), lane = j over 32 consecutive nodes (bw loads
//    128B-coalesced). 5 latent dims/thread, closed-form bubble window:
//      smoothed = (Pg[cnt-1] - inv2*Pm2[cnt-1]) / (cnt - inv2*S2(cnt)).
//    ihalf halves combined through smem P.
// ---------------------------------------------------------------------------
__global__ void __launch_bounds__(512, 2)
main_kernel(const float* __restrict__ bw,
            const int*   __restrict__ neigh,
            float*       __restrict__ out) {
    extern __shared__ float sm[];
    float*          G  = sm;                       // [GSZ]
    float*          W2 = sm + GSZ;                 // [GSZ]
    float*          P  = sm + 2 * GSZ;             // [8][33] half-partials
    unsigned short* NB = (unsigned short*)(sm + 2 * GSZ + BATCH * MSTR); // [1024]

    const int tid    = threadIdx.x;
    const int lane   = tid & 31;
    const int warp   = tid >> 5;
    const int p_base = blockIdx.x * NODES;

    // ---- neighbour tile (input-only: load before PDL sync) ----
    {
        int base = p_base * MU + tid * 2;
        int2 v = make_int2(0, 0);
        if (base + 1 < N_FULL * MU) v = *(const int2*)(neigh + base);
        NB[tid * 2 + 0] = (unsigned short)v.x;
        NB[tid * 2 + 1] = (unsigned short)v.y;
    }
#if defined(__CUDA_ARCH__) && (__CUDA_ARCH__ >= 900)
    cudaGridDependencySynchronize();   // wait for prep_encode results
#endif
    __syncthreads();

    // ---- Phase A: cooperative gather (64 rows/warp, 8 rows per LDG) ----
    {
        const int q  = lane & 3;       // 16B quarter of the 64B row
        const int rl = lane >> 2;      // row-in-instruction 0..7
#pragma unroll
        for (int t = 0; t < 8; t++) {
            const int r = warp * 64 + t * 8 + rl;  // flat row: j=r>>5, m=r&31
            const int m = r & 31;
            const int j = r >> 5;
            const int nb = NB[r];
            if (q < 3) {
                float4 v = __ldg((const float4*)g_dec4 + nb * 4 + q);
                const int a0 = (4 * q) * ISTR + m * MSTR + j;
                G[a0] = v.x;
                G[a0 + ISTR] = v.y;
                if (q < 2) {
                    G[a0 + 2 * ISTR] = v.z;
                    G[a0 + 3 * ISTR] = v.w;
                }
            }
        }
    }
    __syncthreads();

    // ---- Phase B: inclusive prefix over m (320 tasks: i = warp, j = lane) --
    if (tid < NLAT * NODES) {
        const int base = warp * ISTR + lane;       // i = warp, j = lane
        float pg = 0.0f, pm = 0.0f;
#pragma unroll
        for (int m = 0; m < MU; m++) {
            float v = G[base + m * MSTR];
            pg += v;
            pm = fmaf((float)(m * m), v, pm);
            G [base + m * MSTR] = pg;
            W2[base + m * MSTR] = pm;
        }
    }
    __syncthreads();

    // ---- Phase C: warp = (b, ihalf); lane = j over 32 nodes ----
    const int b     = warp >> 1;
    const int ihalf = warp & 1;
    const int j     = lane;
    const int p     = p_base + j;
    const int pc    = (p < N_FULL) ? p : (N_FULL - 1);

    float encb[NLAT];
#pragma unroll
    for (int k = 0; k < NLAT; k++)
        encb[k] = g_encoded[b * NLAT + k];         // bias already included

    const float* bwp = bw + pc;
    float acc = 0.0f;
#pragma unroll
    for (int ii = 0; ii < 5; ii++) {
        const int i = ihalf * 5 + ii;
        float z = 0.0f;
#pragma unroll
        for (int k = 0; k < NLAT; k++)
            z = fmaf(encb[k], __ldg(bwp + (size_t)(i * NLAT + k) * N_FULL), z);

        float e    = __expf(-z);
        float tt   = 1.0f + e;                              // = 1/w
        float u    = __fdividef((float)MU, tt);             // = MU*w
        int   cnt  = min(MU, (int)u + 1);                   // #active m
        float inv2 = tt * tt * (1.0f / (float)(MU * MU));   // 1/(MU*w)^2

        const int base = i * ISTR + (cnt - 1) * MSTR + j;
        float Pg = G[base];
        float Pm = W2[base];
        int   c1 = cnt - 1;
        float S2 = (float)(c1 * cnt * (2 * cnt - 1)) * (1.0f / 6.0f);
        float s  = (float)cnt - inv2 * S2;
        float smv = __fdividef(fmaf(-inv2, Pm, Pg), s);
        acc = fmaf(encb[i], smv, acc);
    }

    // combine the two 5-dim halves through smem
    if (ihalf == 1) P[b * MSTR + j] = acc;
    __syncthreads();
    if (ihalf == 0 && p < N_FULL)
        out[(size_t)b * N_FULL + p] = acc + P[b * MSTR + j];
}

// ---------------------------------------------------------------------------
extern "C" void kernel_launch(void* const* d_in, const int* in_sizes, int n_in,
                              void* d_out, int out_size) {
    const float* x       = (const float*)d_in[0];
    const float* enc_w   = (const float*)d_in[1];
    const float* enc_b   = (const float*)d_in[2];
    const float* decoder = (const float*)d_in[3];
    const float* bw      = (const float*)d_in[4];
    const int*   neigh   = (const int*)  d_in[5];
    float*       out     = (float*)d_out;
    (void)in_sizes; (void)n_in; (void)out_size;

    const int tp_blocks = (N_FULL + 255) / 256;                 // 196
    prep_encode_kernel<<<BATCH * NLAT + tp_blocks, 256>>>(x, enc_w, enc_b,
                                                          decoder);

    size_t smem_bytes = (size_t)(2 * GSZ + BATCH * MSTR) * sizeof(float)
                      + (size_t)(NODES * MU) * sizeof(unsigned short);
    cudaFuncSetAttribute(main_kernel,
                         cudaFuncAttributeMaxDynamicSharedMemorySize,
                         (int)smem_bytes);

    // main with PDL: overlap its prologue with prep_encode execution
    cudaLaunchConfig_t cfg = {};
    cfg.gridDim  = dim3((N_FULL + NODES - 1) / NODES);   // 1563
    cfg.blockDim = dim3(512);
    cfg.dynamicSmemBytes = smem_bytes;
    cfg.stream = 0;
    cudaLaunchAttribute attr[1];
    attr[0].id = cudaLaunchAttributeProgrammaticStreamSerialization;
    attr[0].val.programmaticStreamSerializationAllowed = 1;
    cfg.attrs = attr;
    cfg.numAttrs = 1;
    if (cudaLaunchKernelEx(&cfg, main_kernel, bw, neigh, out) != cudaSuccess) {
        main_kernel<<<(N_FULL + NODES - 1) / NODES, 512, smem_bytes>>>(
            bw, neigh, out);
    }
}